// round 10
// baseline (speedup 1.0000x reference)
#include <cuda_runtime.h>

// MaskedNorm: X[B,N,D] fp32, mask[B,N] int32 (1 == masked out), W[D], b[D].
// out = mask ? b : (X - mean_n)/std_n * W + b   (std unbiased, ddof=1; REPLACE=0)
#define Bz 64
#define Nz 8192
#define Dz 128
#define D4 32                          // D/4 float4 lanes
#define SPLITS 16                      // stats chunks per batch
#define ROWS_PER_SPLIT (Nz / SPLITS)   // 512
#define RPB 256                        // rows per norm chunk
#define NCHUNKS (Nz / RPB)             // 32 norm chunks per batch
#define TPB (SPLITS + NCHUNKS)         // 48 tasks per batch
#define TOTAL_TASKS (Bz * TPB)         // 3072
#define GBLK 512                       // persistent blocks (resident: >=4/SM*148=592)

// Per-split partials: every slot overwritten each launch (no zeroing needed).
__device__ float g_psum[SPLITS][Bz * Dz];
__device__ float g_psq [SPLITS][Bz * Dz];
__device__ int   g_pcnt[SPLITS][Bz];
__device__ int   g_ready[Bz];          // completed stats chunks per batch (zeroed)

__global__ void mn_zero_kernel() {
    int i = threadIdx.x;
    if (i < Bz) g_ready[i] = 0;
}

// Persistent fused kernel.  Combined task list, batch-major:
//   task t: b = t/48, j = t%48.  j<16 -> stats chunk j;  j>=16 -> norm chunk j-16.
// Block g executes tasks g, g+GBLK, g+2*GBLK, ... in order.  Norm tasks spin on
// g_ready[b]==SPLITS.  Progress: all GBLK blocks resident (launch_bounds 4/SM),
// and the smallest-position incomplete task is always runnable.
__global__ void __launch_bounds__(256, 4)
mn_fused_kernel(const float* __restrict__ X,
                const int* __restrict__ mask,
                const float* __restrict__ W,
                const float* __restrict__ bias,
                float* __restrict__ out) {
    const int tid = threadIdx.x;
    const int d4  = tid & 31;          // float4 lane in D
    const int rg  = tid >> 5;          // warp id 0..7
    const int dd  = d4 * 4;

    __shared__ float ssum[8][Dz];
    __shared__ float ssq [8][Dz];
    __shared__ int   scnt[8];
    __shared__ float sa[Dz];           // W * invstd
    __shared__ float sc[Dz];           // bias - mean * W * invstd
    __shared__ float sr[Dz];           // replacement: bias

    for (int t = blockIdx.x; t < TOTAL_TASKS; t += GBLK) {
        const int b = t / TPB;
        const int j = t % TPB;

        const float4* Xb = (const float4*)(X + (size_t)b * Nz * Dz);
        const int*    mb = mask + (size_t)b * Nz;

        if (j < SPLITS) {
            // ---------------- stats chunk ----------------
            const int row0 = j * ROWS_PER_SPLIT;

            float4 s = make_float4(0.f, 0.f, 0.f, 0.f);
            float4 q = make_float4(0.f, 0.f, 0.f, 0.f);
            int cnt = 0;

            for (int r = row0 + rg; r < row0 + ROWS_PER_SPLIT; r += 8) {
                int m = mb[r];                       // warp-uniform
                if (!m) {
                    float4 v = Xb[(size_t)r * D4 + d4];
                    s.x += v.x; s.y += v.y; s.z += v.z; s.w += v.w;
                    q.x = fmaf(v.x, v.x, q.x); q.y = fmaf(v.y, v.y, q.y);
                    q.z = fmaf(v.z, v.z, q.z); q.w = fmaf(v.w, v.w, q.w);
                    cnt++;
                }
            }

            ((float4*)&ssum[rg][0])[d4] = s;
            ((float4*)&ssq [rg][0])[d4] = q;
            if (d4 == 0) scnt[rg] = cnt;
            __syncthreads();

            if (tid < Dz) {
                float ts = 0.f, tq = 0.f;
                #pragma unroll
                for (int i = 0; i < 8; i++) { ts += ssum[i][tid]; tq += ssq[i][tid]; }
                g_psum[j][b * Dz + tid] = ts;
                g_psq [j][b * Dz + tid] = tq;
            }
            if (tid == 0) {
                int c = 0;
                #pragma unroll
                for (int i = 0; i < 8; i++) c += scnt[i];
                g_pcnt[j][b] = c;
            }
            __threadfence();                         // publish partials
            __syncthreads();
            if (tid == 0) atomicAdd(&g_ready[b], 1);
            __syncthreads();                         // smem reuse barrier
        } else {
            // ---------------- norm chunk ----------------
            if (tid == 0) {
                while (*((volatile int*)&g_ready[b]) < SPLITS) { }
                __threadfence();                     // acquire partials
            }
            __syncthreads();

            if (tid < Dz) {
                float ts = 0.f, tq = 0.f;
                int   c  = 0;
                #pragma unroll
                for (int s = 0; s < SPLITS; s++) {
                    ts += g_psum[s][b * Dz + tid];
                    tq += g_psq [s][b * Dz + tid];
                    c  += g_pcnt[s][b];
                }
                float fc   = (float)c;
                float mean = ts / fc;
                float var  = (tq - fc * mean * mean) / (fc - 1.0f);
                float inv  = rsqrtf(var);
                float w    = W[tid];
                float bb   = bias[tid];
                float a    = w * inv;
                sa[tid] = a;
                sc[tid] = bb - mean * a;
                sr[tid] = bb;
            }
            __syncthreads();

            const int row0 = (j - SPLITS) * RPB;
            float4* Ob = (float4*)(out + (size_t)b * Nz * Dz);

            const float a0 = sa[dd], a1 = sa[dd + 1], a2 = sa[dd + 2], a3 = sa[dd + 3];
            const float c0 = sc[dd], c1 = sc[dd + 1], c2 = sc[dd + 2], c3 = sc[dd + 3];
            float4 rv;
            rv.x = sr[dd]; rv.y = sr[dd + 1]; rv.z = sr[dd + 2]; rv.w = sr[dd + 3];

            // 32 rows/warp, unroll 4; all loads unconditional (masked rows
            // redirected to L2-hot batch row 0); .cs policies on the streams.
            for (int r = row0 + rg; r < row0 + RPB; r += 32) {
                const int rA = r, rB = r + 8, rC = r + 16, rD = r + 24;
                const int m0 = mb[rA];
                const int m1 = mb[rB];
                const int m2 = mb[rC];
                const int m3 = mb[rD];

                const size_t i0 = m0 ? (size_t)d4 : (size_t)rA * D4 + d4;
                const size_t i1 = m1 ? (size_t)d4 : (size_t)rB * D4 + d4;
                const size_t i2 = m2 ? (size_t)d4 : (size_t)rC * D4 + d4;
                const size_t i3 = m3 ? (size_t)d4 : (size_t)rD * D4 + d4;

                const float4 v0 = __ldcs(&Xb[i0]);
                const float4 v1 = __ldcs(&Xb[i1]);
                const float4 v2 = __ldcs(&Xb[i2]);
                const float4 v3 = __ldcs(&Xb[i3]);

                float4 o0, o1, o2, o3;
                o0.x = m0 ? rv.x : fmaf(v0.x, a0, c0);
                o0.y = m0 ? rv.y : fmaf(v0.y, a1, c1);
                o0.z = m0 ? rv.z : fmaf(v0.z, a2, c2);
                o0.w = m0 ? rv.w : fmaf(v0.w, a3, c3);

                o1.x = m1 ? rv.x : fmaf(v1.x, a0, c0);
                o1.y = m1 ? rv.y : fmaf(v1.y, a1, c1);
                o1.z = m1 ? rv.z : fmaf(v1.z, a2, c2);
                o1.w = m1 ? rv.w : fmaf(v1.w, a3, c3);

                o2.x = m2 ? rv.x : fmaf(v2.x, a0, c0);
                o2.y = m2 ? rv.y : fmaf(v2.y, a1, c1);
                o2.z = m2 ? rv.z : fmaf(v2.z, a2, c2);
                o2.w = m2 ? rv.w : fmaf(v2.w, a3, c3);

                o3.x = m3 ? rv.x : fmaf(v3.x, a0, c0);
                o3.y = m3 ? rv.y : fmaf(v3.y, a1, c1);
                o3.z = m3 ? rv.z : fmaf(v3.z, a2, c2);
                o3.w = m3 ? rv.w : fmaf(v3.w, a3, c3);

                __stcs(&Ob[(size_t)rA * D4 + d4], o0);
                __stcs(&Ob[(size_t)rB * D4 + d4], o1);
                __stcs(&Ob[(size_t)rC * D4 + d4], o2);
                __stcs(&Ob[(size_t)rD * D4 + d4], o3);
            }
            __syncthreads();                         // smem reuse barrier
        }
    }
}

extern "C" void kernel_launch(void* const* d_in, const int* in_sizes, int n_in,
                              void* d_out, int out_size) {
    const float* X    = (const float*)d_in[0];
    const int*   mask = (const int*)d_in[1];
    const float* W    = (const float*)d_in[2];
    const float* bias = (const float*)d_in[3];
    float* out        = (float*)d_out;

    mn_zero_kernel<<<1, 64>>>();
    mn_fused_kernel<<<GBLK, 256>>>(X, mask, W, bias, out);
}

// round 11
// speedup vs baseline: 1.6621x; 1.6621x over previous
#include <cuda_runtime.h>

// MaskedNorm: X[B,N,D] fp32, mask[B,N] int32 (1 == masked out), W[D], b[D].
// out = mask ? b : (X - mean_n)/std_n * W + b   (std unbiased, ddof=1; REPLACE=0)
#define Bz 64
#define Nz 8192
#define Dz 128
#define D4 32          // D/4 float4 lanes
#define SPLITS 16      // stats blocks per batch
#define ROWS_PER_SPLIT (Nz / SPLITS)   // 512
#define RPB 256        // rows per block in normalize kernel
#define CACHED_B 40    // trailing batches whose X lines we deliberately keep in L2

// Per-split partials: every slot is overwritten on every launch.
// -> no zero kernel, no atomics, deterministic under graph replay.
__device__ float g_psum[SPLITS][Bz * Dz];
__device__ float g_psq [SPLITS][Bz * Dz];
__device__ int   g_pcnt[SPLITS][Bz];

// grid (SPLITS, B), block 256.  warp w handles rows row0+w, row0+w+8, ...
// Cache-policy partition: batches < Bz-CACHED_B stream through L2 (.cs,
// evict-first -> they never churn the cache); batches >= Bz-CACHED_B use the
// default policy so their valid lines (~80MB < 126MB L2) stay resident for
// the norm kernel.
__global__ void mn_stats_kernel(const float* __restrict__ X,
                                const int* __restrict__ mask) {
    const int b     = blockIdx.y;
    const int split = blockIdx.x;
    const int tid   = threadIdx.x;
    const int d4    = tid & 31;    // float4 lane in D
    const int rg    = tid >> 5;    // row group 0..7 (== warp id)
    const int row0  = split * ROWS_PER_SPLIT;
    const bool keep = (b >= Bz - CACHED_B);

    const float4* Xb = (const float4*)(X + (size_t)b * Nz * Dz);
    const int*    mb = mask + (size_t)b * Nz;

    float4 s = make_float4(0.f, 0.f, 0.f, 0.f);
    float4 q = make_float4(0.f, 0.f, 0.f, 0.f);
    int cnt = 0;

    for (int r = row0 + rg; r < row0 + ROWS_PER_SPLIT; r += 8) {
        int m = mb[r];                         // uniform per warp (broadcast)
        if (!m) {
            float4 v = keep ? Xb[(size_t)r * D4 + d4]
                            : __ldcs(&Xb[(size_t)r * D4 + d4]);
            s.x += v.x; s.y += v.y; s.z += v.z; s.w += v.w;
            q.x = fmaf(v.x, v.x, q.x); q.y = fmaf(v.y, v.y, q.y);
            q.z = fmaf(v.z, v.z, q.z); q.w = fmaf(v.w, v.w, q.w);
            cnt++;
        }
    }

    __shared__ float ssum[8][Dz];
    __shared__ float ssq[8][Dz];
    __shared__ int   scnt[8];
    ((float4*)&ssum[rg][0])[d4] = s;
    ((float4*)&ssq[rg][0])[d4]  = q;
    if (d4 == 0) scnt[rg] = cnt;
    __syncthreads();

    if (tid < Dz) {
        float ts = 0.f, tq = 0.f;
        #pragma unroll
        for (int i = 0; i < 8; i++) { ts += ssum[i][tid]; tq += ssq[i][tid]; }
        g_psum[split][b * Dz + tid] = ts;      // plain store, overwritten every launch
        g_psq [split][b * Dz + tid] = tq;
    }
    if (tid == 0) {
        int c = 0;
        #pragma unroll
        for (int i = 0; i < 8; i++) c += scnt[i];
        g_pcnt[split][b] = c;
    }
}

// grid (N/RPB, B), block 256.
// LIFO batch traversal (b = Bz-1 - blockIdx.y): the kept batches (tail) are
// consumed first while resident.  Loads use .cs (hit-if-present, dead after
// read), stores use .cs (evict-first; don't evict the kept stats lines).
__global__ void mn_norm_kernel(const float* __restrict__ X,
                               const int* __restrict__ mask,
                               const float* __restrict__ W,
                               const float* __restrict__ bias,
                               float* __restrict__ out) {
    const int b   = Bz - 1 - blockIdx.y;    // reverse: kept batches first
    const int tid = threadIdx.x;

    __shared__ float sa[Dz];   // W * invstd
    __shared__ float sc[Dz];   // bias - mean * W * invstd
    __shared__ float sr[Dz];   // replacement value: 0*W + bias

    if (tid < Dz) {
        float ts = 0.f, tq = 0.f;
        int   c  = 0;
        #pragma unroll
        for (int s = 0; s < SPLITS; s++) {
            ts += g_psum[s][b * Dz + tid];
            tq += g_psq [s][b * Dz + tid];
            c  += g_pcnt[s][b];
        }
        float fc   = (float)c;
        float mean = ts / fc;
        float var  = (tq - fc * mean * mean) / (fc - 1.0f);
        float inv  = rsqrtf(var);
        float w    = W[tid];
        float bb   = bias[tid];
        float a    = w * inv;
        sa[tid] = a;
        sc[tid] = bb - mean * a;
        sr[tid] = bb;
    }
    __syncthreads();

    const int d4   = tid & 31;
    const int rg   = tid >> 5;
    const int row0 = blockIdx.x * RPB;
    const int dd   = d4 * 4;

    const float4* Xb = (const float4*)(X + (size_t)b * Nz * Dz);
    float4*       Ob = (float4*)(out + (size_t)b * Nz * Dz);
    const int*    mb = mask + (size_t)b * Nz;

    const float a0 = sa[dd], a1 = sa[dd + 1], a2 = sa[dd + 2], a3 = sa[dd + 3];
    const float c0 = sc[dd], c1 = sc[dd + 1], c2 = sc[dd + 2], c3 = sc[dd + 3];
    float4 rv;
    rv.x = sr[dd]; rv.y = sr[dd + 1]; rv.z = sr[dd + 2]; rv.w = sr[dd + 3];

    // 32 rows per warp, unroll 4.  All loads unconditional (full MLP); masked
    // rows read batch row 0 (512B, always hot) so they cost no DRAM bandwidth.
    for (int r = row0 + rg; r < row0 + RPB; r += 32) {
        const int rA = r, rB = r + 8, rC = r + 16, rD = r + 24;
        const int m0 = mb[rA];
        const int m1 = mb[rB];
        const int m2 = mb[rC];
        const int m3 = mb[rD];

        const size_t i0 = m0 ? (size_t)d4 : (size_t)rA * D4 + d4;
        const size_t i1 = m1 ? (size_t)d4 : (size_t)rB * D4 + d4;
        const size_t i2 = m2 ? (size_t)d4 : (size_t)rC * D4 + d4;
        const size_t i3 = m3 ? (size_t)d4 : (size_t)rD * D4 + d4;

        const float4 v0 = __ldcs(&Xb[i0]);
        const float4 v1 = __ldcs(&Xb[i1]);
        const float4 v2 = __ldcs(&Xb[i2]);
        const float4 v3 = __ldcs(&Xb[i3]);

        float4 o0, o1, o2, o3;
        o0.x = m0 ? rv.x : fmaf(v0.x, a0, c0);
        o0.y = m0 ? rv.y : fmaf(v0.y, a1, c1);
        o0.z = m0 ? rv.z : fmaf(v0.z, a2, c2);
        o0.w = m0 ? rv.w : fmaf(v0.w, a3, c3);

        o1.x = m1 ? rv.x : fmaf(v1.x, a0, c0);
        o1.y = m1 ? rv.y : fmaf(v1.y, a1, c1);
        o1.z = m1 ? rv.z : fmaf(v1.z, a2, c2);
        o1.w = m1 ? rv.w : fmaf(v1.w, a3, c3);

        o2.x = m2 ? rv.x : fmaf(v2.x, a0, c0);
        o2.y = m2 ? rv.y : fmaf(v2.y, a1, c1);
        o2.z = m2 ? rv.z : fmaf(v2.z, a2, c2);
        o2.w = m2 ? rv.w : fmaf(v2.w, a3, c3);

        o3.x = m3 ? rv.x : fmaf(v3.x, a0, c0);
        o3.y = m3 ? rv.y : fmaf(v3.y, a1, c1);
        o3.z = m3 ? rv.z : fmaf(v3.z, a2, c2);
        o3.w = m3 ? rv.w : fmaf(v3.w, a3, c3);

        __stcs(&Ob[(size_t)rA * D4 + d4], o0);
        __stcs(&Ob[(size_t)rB * D4 + d4], o1);
        __stcs(&Ob[(size_t)rC * D4 + d4], o2);
        __stcs(&Ob[(size_t)rD * D4 + d4], o3);
    }
}

extern "C" void kernel_launch(void* const* d_in, const int* in_sizes, int n_in,
                              void* d_out, int out_size) {
    const float* X    = (const float*)d_in[0];
    const int*   mask = (const int*)d_in[1];
    const float* W    = (const float*)d_in[2];
    const float* bias = (const float*)d_in[3];
    float* out        = (float*)d_out;

    dim3 g1(SPLITS, Bz);
    mn_stats_kernel<<<g1, 256>>>(X, mask);

    dim3 g2(Nz / RPB, Bz);
    mn_norm_kernel<<<g2, 256>>>(X, mask, W, bias, out);
}

// round 12
// speedup vs baseline: 1.6851x; 1.0138x over previous
#include <cuda_runtime.h>

// MaskedNorm: X[B,N,D] fp32, mask[B,N] int32 (1 == masked out), W[D], b[D].
// out = mask ? b : (X - mean_n)/std_n * W + b   (std unbiased, ddof=1; REPLACE=0)
#define Bz 64
#define Nz 8192
#define Dz 128
#define D4 32          // D/4 float4 lanes
#define SPLITS 16      // stats blocks per batch
#define ROWS_PER_SPLIT (Nz / SPLITS)   // 512
#define RPB 256        // rows per block in normalize kernel

// Per-split partials: every slot is overwritten on every launch.
// -> no zero kernel, no atomics, deterministic under graph replay.
__device__ float g_psum[SPLITS][Bz * Dz];
__device__ float g_psq [SPLITS][Bz * Dz];
__device__ int   g_pcnt[SPLITS][Bz];

// grid (SPLITS, B), block 256.  warp w handles rows row0+w, row0+w+8, ...
// Default load policy: valid X lines stay resident in L2 for the norm kernel.
__global__ void mn_stats_kernel(const float* __restrict__ X,
                                const int* __restrict__ mask) {
    const int b     = blockIdx.y;
    const int split = blockIdx.x;
    const int tid   = threadIdx.x;
    const int d4    = tid & 31;    // float4 lane in D
    const int rg    = tid >> 5;    // row group 0..7 (== warp id)
    const int row0  = split * ROWS_PER_SPLIT;

    const float4* Xb = (const float4*)(X + (size_t)b * Nz * Dz);
    const int*    mb = mask + (size_t)b * Nz;

    float4 s = make_float4(0.f, 0.f, 0.f, 0.f);
    float4 q = make_float4(0.f, 0.f, 0.f, 0.f);
    int cnt = 0;

    for (int r = row0 + rg; r < row0 + ROWS_PER_SPLIT; r += 8) {
        int m = mb[r];                         // uniform per warp (broadcast)
        if (!m) {
            float4 v = Xb[(size_t)r * D4 + d4];
            s.x += v.x; s.y += v.y; s.z += v.z; s.w += v.w;
            q.x = fmaf(v.x, v.x, q.x); q.y = fmaf(v.y, v.y, q.y);
            q.z = fmaf(v.z, v.z, q.z); q.w = fmaf(v.w, v.w, q.w);
            cnt++;
        }
    }

    __shared__ float ssum[8][Dz];
    __shared__ float ssq[8][Dz];
    __shared__ int   scnt[8];
    ((float4*)&ssum[rg][0])[d4] = s;
    ((float4*)&ssq[rg][0])[d4]  = q;
    if (d4 == 0) scnt[rg] = cnt;
    __syncthreads();

    if (tid < Dz) {
        float ts = 0.f, tq = 0.f;
        #pragma unroll
        for (int i = 0; i < 8; i++) { ts += ssum[i][tid]; tq += ssq[i][tid]; }
        g_psum[split][b * Dz + tid] = ts;      // plain store, overwritten every launch
        g_psq [split][b * Dz + tid] = tq;
    }
    if (tid == 0) {
        int c = 0;
        #pragma unroll
        for (int i = 0; i < 8; i++) c += scnt[i];
        g_pcnt[split][b] = c;
    }
}

// grid (N/RPB, B), block 256.
// LIFO batch traversal (b = Bz-1 - blockIdx.y) to harvest the L2-resident tail
// of the stats read set.  Loads .cs (dead after read), stores .cs (evict-first).
// Unroll 2 (not 4) so live state fits 6 blocks/SM without spilling:
// __launch_bounds__(256, 6) -> 48 warps/SM for more latency hiding.
__global__ void __launch_bounds__(256, 6)
mn_norm_kernel(const float* __restrict__ X,
               const int* __restrict__ mask,
               const float* __restrict__ W,
               const float* __restrict__ bias,
               float* __restrict__ out) {
    const int b   = Bz - 1 - blockIdx.y;    // reverse: most-recently-warmed first
    const int tid = threadIdx.x;

    __shared__ float sa[Dz];   // W * invstd
    __shared__ float sc[Dz];   // bias - mean * W * invstd
    __shared__ float sr[Dz];   // replacement value: 0*W + bias

    if (tid < Dz) {
        float ts = 0.f, tq = 0.f;
        int   c  = 0;
        #pragma unroll
        for (int s = 0; s < SPLITS; s++) {
            ts += g_psum[s][b * Dz + tid];
            tq += g_psq [s][b * Dz + tid];
            c  += g_pcnt[s][b];
        }
        float fc   = (float)c;
        float mean = ts / fc;
        float var  = (tq - fc * mean * mean) / (fc - 1.0f);
        float inv  = rsqrtf(var);
        float w    = W[tid];
        float bb   = bias[tid];
        float a    = w * inv;
        sa[tid] = a;
        sc[tid] = bb - mean * a;
        sr[tid] = bb;
    }
    __syncthreads();

    const int d4   = tid & 31;
    const int rg   = tid >> 5;
    const int row0 = blockIdx.x * RPB;
    const int dd   = d4 * 4;

    const float4* Xb = (const float4*)(X + (size_t)b * Nz * Dz);
    float4*       Ob = (float4*)(out + (size_t)b * Nz * Dz);
    const int*    mb = mask + (size_t)b * Nz;

    const float a0 = sa[dd], a1 = sa[dd + 1], a2 = sa[dd + 2], a3 = sa[dd + 3];
    const float c0 = sc[dd], c1 = sc[dd + 1], c2 = sc[dd + 2], c3 = sc[dd + 3];
    float4 rv;
    rv.x = sr[dd]; rv.y = sr[dd + 1]; rv.z = sr[dd + 2]; rv.w = sr[dd + 3];

    // 32 rows per warp, unroll 2.  All loads unconditional (masked rows
    // redirected to L2-hot batch row 0 -> no DRAM cost); FSEL output select.
    for (int r = row0 + rg; r < row0 + RPB; r += 16) {
        const int rA = r, rB = r + 8;
        const int m0 = mb[rA];
        const int m1 = mb[rB];

        const size_t i0 = m0 ? (size_t)d4 : (size_t)rA * D4 + d4;
        const size_t i1 = m1 ? (size_t)d4 : (size_t)rB * D4 + d4;

        const float4 v0 = __ldcs(&Xb[i0]);
        const float4 v1 = __ldcs(&Xb[i1]);

        float4 o0, o1;
        o0.x = m0 ? rv.x : fmaf(v0.x, a0, c0);
        o0.y = m0 ? rv.y : fmaf(v0.y, a1, c1);
        o0.z = m0 ? rv.z : fmaf(v0.z, a2, c2);
        o0.w = m0 ? rv.w : fmaf(v0.w, a3, c3);

        o1.x = m1 ? rv.x : fmaf(v1.x, a0, c0);
        o1.y = m1 ? rv.y : fmaf(v1.y, a1, c1);
        o1.z = m1 ? rv.z : fmaf(v1.z, a2, c2);
        o1.w = m1 ? rv.w : fmaf(v1.w, a3, c3);

        __stcs(&Ob[(size_t)rA * D4 + d4], o0);
        __stcs(&Ob[(size_t)rB * D4 + d4], o1);
    }
}

extern "C" void kernel_launch(void* const* d_in, const int* in_sizes, int n_in,
                              void* d_out, int out_size) {
    const float* X    = (const float*)d_in[0];
    const int*   mask = (const int*)d_in[1];
    const float* W    = (const float*)d_in[2];
    const float* bias = (const float*)d_in[3];
    float* out        = (float*)d_out;

    dim3 g1(SPLITS, Bz);
    mn_stats_kernel<<<g1, 256>>>(X, mask);

    dim3 g2(Nz / RPB, Bz);
    mn_norm_kernel<<<g2, 256>>>(X, mask, W, bias, out);
}